// round 1
// baseline (speedup 1.0000x reference)
#include <cuda_runtime.h>
#include <math_constants.h>

#define N_ROWS  16384       // b*h*w = 16*32*32
#define D_DIM   256
#define K_CODES 8192
#define HW      1024        // h*w
#define ZQ_ELEMS (16 * 256 * 1024)   // 4194304

// ---------------- scratch (static __device__, no allocation) ----------------
__device__ float g_zt[N_ROWS * D_DIM];     // z transposed to [n][d], 16 MB
__device__ float g_znorm[N_ROWS];
__device__ float g_enorm[K_CODES];
__device__ int   g_idx[N_ROWS];
__device__ float g_partial[4096];

// ---------------- kernel 1: transpose z [b,c,hw] -> zt [b*hw, c] ------------
__global__ void k_transpose(const float* __restrict__ z) {
    __shared__ float t[32][33];
    const int b   = blockIdx.z;
    const int c0  = blockIdx.x * 32;
    const int hw0 = blockIdx.y * 32;
    const int tx = threadIdx.x & 31, ty = threadIdx.x >> 5;  // ty in [0,8)
    const float* zp = z + ((size_t)b * 256 + c0) * HW + hw0;
#pragma unroll
    for (int i = 0; i < 4; i++)
        t[ty + i * 8][tx] = zp[(size_t)(ty + i * 8) * HW + tx];
    __syncthreads();
    float* o = g_zt + ((size_t)(b * HW + hw0)) * D_DIM + c0;
#pragma unroll
    for (int i = 0; i < 4; i++)
        o[(size_t)(ty + i * 8) * D_DIM + tx] = t[tx][ty + i * 8];
}

// ---------------- kernel 2: row norms for z and codebook --------------------
__global__ void k_norms(const float* __restrict__ cb) {
    const int warp = (blockIdx.x * 256 + threadIdx.x) >> 5;
    const int lane = threadIdx.x & 31;
    const float* src = (warp < N_ROWS) ? (g_zt + (size_t)warp * D_DIM)
                                       : (cb + (size_t)(warp - N_ROWS) * D_DIM);
    float s = 0.f;
#pragma unroll
    for (int i = 0; i < 8; i++) {
        float v = src[lane + i * 32];
        s = fmaf(v, v, s);
    }
#pragma unroll
    for (int o = 16; o; o >>= 1) s += __shfl_xor_sync(0xffffffffu, s, o);
    if (lane == 0) {
        if (warp < N_ROWS) g_znorm[warp] = s;
        else               g_enorm[warp - N_ROWS] = s;
    }
}

// ---------------- kernel 3: fused distance GEMM + row argmin ----------------
// Tile: TM=128 rows x TN=64 codes per block, 256 threads (16x16), 8x4 microtile.
#define TM 128
#define TN 64
#define DK 32
#define APAD 132
#define BPAD 68

__global__ __launch_bounds__(256, 1)
void k_argmin(const float* __restrict__ cb, float* __restrict__ oidx) {
    __shared__ float As[DK * APAD];   // [k][row], padded (16B-aligned rows)
    __shared__ float Bs[DK * BPAD];   // [k][col], padded
    const int tid = threadIdx.x;
    const int tx = tid & 15, ty = tid >> 4;
    const int row0 = blockIdx.x * TM;

    float zn[8], dmin[8];
    int   imin[8];
#pragma unroll
    for (int i = 0; i < 8; i++) {
        zn[i]   = g_znorm[row0 + ty * 8 + i];
        dmin[i] = CUDART_INF_F;
        imin[i] = 0;
    }

    const int lr = tid >> 3;          // 0..31
    const int lc = (tid & 7) * 4;     // 0..28

    for (int kt = 0; kt < K_CODES; kt += TN) {
        float acc[8][4];
#pragma unroll
        for (int i = 0; i < 8; i++)
#pragma unroll
            for (int j = 0; j < 4; j++) acc[i][j] = 0.f;

        for (int dk = 0; dk < D_DIM; dk += DK) {
            __syncthreads();
            // stage A (z rows), transposed into [k][row]
            const float* ap = g_zt + (size_t)row0 * D_DIM + dk;
#pragma unroll
            for (int i = 0; i < 4; i++) {
                float4 v = *(const float4*)(ap + (size_t)(lr + i * 32) * D_DIM + lc);
                As[(lc + 0) * APAD + lr + i * 32] = v.x;
                As[(lc + 1) * APAD + lr + i * 32] = v.y;
                As[(lc + 2) * APAD + lr + i * 32] = v.z;
                As[(lc + 3) * APAD + lr + i * 32] = v.w;
            }
            // stage B (codebook rows), transposed into [k][col]
            const float* bp = cb + (size_t)kt * D_DIM + dk;
#pragma unroll
            for (int i = 0; i < 2; i++) {
                float4 v = *(const float4*)(bp + (size_t)(lr + i * 32) * D_DIM + lc);
                Bs[(lc + 0) * BPAD + lr + i * 32] = v.x;
                Bs[(lc + 1) * BPAD + lr + i * 32] = v.y;
                Bs[(lc + 2) * BPAD + lr + i * 32] = v.z;
                Bs[(lc + 3) * BPAD + lr + i * 32] = v.w;
            }
            __syncthreads();
#pragma unroll
            for (int kk = 0; kk < DK; kk++) {
                float a[8], b[4];
                *(float4*)(a)     = *(const float4*)(&As[kk * APAD + ty * 8]);
                *(float4*)(a + 4) = *(const float4*)(&As[kk * APAD + ty * 8 + 4]);
                *(float4*)(b)     = *(const float4*)(&Bs[kk * BPAD + tx * 4]);
#pragma unroll
                for (int i = 0; i < 8; i++)
#pragma unroll
                    for (int j = 0; j < 4; j++)
                        acc[i][j] = fmaf(a[i], b[j], acc[i][j]);
            }
        }
        // epilogue: replicate reference rounding  d = (zn + en) - 2*dot,
        // ascending-k + strict '<' => first-index tie-break like jnp.argmin.
#pragma unroll
        for (int j = 0; j < 4; j++) {
            const int k = kt + tx * 4 + j;
            const float en = __ldg(&g_enorm[k]);
#pragma unroll
            for (int i = 0; i < 8; i++) {
                float s   = zn[i] + en;          // plain add (no contraction)
                float dsc = s - 2.0f * acc[i][j]; // 2*acc exact, single rounding
                if (dsc < dmin[i]) { dmin[i] = dsc; imin[i] = k; }
            }
        }
    }

    // cross-thread (tx) reduction per row, lexicographic (d, idx)
    __syncthreads();
    float* redD = As;           // 128*16 floats fits in As
    int*   redI = (int*)Bs;     // 128*16 ints fits in Bs
#pragma unroll
    for (int i = 0; i < 8; i++) {
        const int r = ty * 8 + i;
        redD[r * 16 + tx] = dmin[i];
        redI[r * 16 + tx] = imin[i];
    }
    __syncthreads();
    if (tid < TM) {
        float best = redD[tid * 16];
        int   bi   = redI[tid * 16];
#pragma unroll
        for (int t = 1; t < 16; t++) {
            float d = redD[tid * 16 + t];
            int  ii = redI[tid * 16 + t];
            if (d < best || (d == best && ii < bi)) { best = d; bi = ii; }
        }
        g_idx[row0 + tid] = bi;
        oidx[row0 + tid]  = (float)bi;   // min_idx output (as float)
    }
}

// ---------------- kernel 4: gather + straight-through + loss partials -------
// grid (256 c, 16 b), 256 threads over hw. Replicates out = z + (zq - z).
__global__ void k_gather(const float* __restrict__ z, const float* __restrict__ cb,
                         float* __restrict__ out) {
    const int c = blockIdx.x, b = blockIdx.y;
    const float* zp = z   + ((size_t)b * D_DIM + c) * HW;
    float*       op = out + ((size_t)b * D_DIM + c) * HW;
    float part = 0.f;
#pragma unroll
    for (int it = 0; it < 4; it++) {
        const int hw  = it * 256 + threadIdx.x;
        const int idx = g_idx[b * HW + hw];
        float q  = __ldg(cb + (size_t)idx * D_DIM + c);
        float zv = zp[hw];
        float t  = q - zv;          // fl(zq - z)
        op[hw]   = zv + t;          // fl(z + t)  (straight-through rounding)
        part     = fmaf(t, t, part);
    }
    __shared__ float sm[8];
    const int lane = threadIdx.x & 31, w = threadIdx.x >> 5;
#pragma unroll
    for (int o = 16; o; o >>= 1) part += __shfl_xor_sync(0xffffffffu, part, o);
    if (lane == 0) sm[w] = part;
    __syncthreads();
    if (threadIdx.x == 0) {
        float s = 0.f;
        for (int i = 0; i < 8; i++) s += sm[i];   // fixed order: deterministic
        g_partial[b * 256 + c] = s;
    }
}

// ---------------- kernel 5: deterministic loss finalize ---------------------
__global__ void k_loss(float* __restrict__ out) {
    __shared__ float sm[256];
    const int tid = threadIdx.x;
    float s = 0.f;
#pragma unroll
    for (int i = 0; i < 16; i++) s += g_partial[tid * 16 + i];
    sm[tid] = s;
    __syncthreads();
    for (int o = 128; o; o >>= 1) {
        if (tid < o) sm[tid] += sm[tid + o];
        __syncthreads();
    }
    if (tid == 0) {
        float m = sm[0] / (float)ZQ_ELEMS;
        out[ZQ_ELEMS] = m + 0.25f * m;   // mean1 + beta*mean2 (identical means)
    }
}

// ---------------- launcher ---------------------------------------------------
extern "C" void kernel_launch(void* const* d_in, const int* in_sizes, int n_in,
                              void* d_out, int out_size) {
    const float* z  = (const float*)d_in[0];
    const float* cb = (const float*)d_in[1];
    float* out = (float*)d_out;

    dim3 gT(8, 32, 16);                 // c-tiles, hw-tiles, b
    k_transpose<<<gT, 256>>>(z);
    k_norms<<<(N_ROWS + K_CODES) / 8, 256>>>(cb);
    k_argmin<<<N_ROWS / TM, 256>>>(cb, out + ZQ_ELEMS + 1);
    dim3 gG(256, 16);                   // c, b
    k_gather<<<gG, 256>>>(z, cb, out);
    k_loss<<<1, 256>>>(out);
}

// round 3
// speedup vs baseline: 5.2959x; 5.2959x over previous
#include <cuda_runtime.h>
#include <cuda_bf16.h>
#include <math_constants.h>
#include <cstdint>

#define N_ROWS  16384       // b*h*w
#define D_DIM   256
#define K_CODES 8192
#define HW      1024
#define ZQ_ELEMS (16 * 256 * 1024)
#define NT      64          // code tiles of 128
#define C1_T    1.25e-6f    // per-row error slope (covers bf16 rounding of z,e)
#define C0_T    1.6e-4f     // fixed slack: fp32 reorder + expr rounding + grid ulps

// ---------------- scratch ----------------------------------------------------
__device__ __align__(16) float          g_zt[N_ROWS * D_DIM];
__device__ __align__(16) __nv_bfloat16  g_zbf[N_ROWS * D_DIM];
__device__ __align__(16) __nv_bfloat16  g_cbbf[K_CODES * D_DIM];
__device__ float g_znorm[N_ROWS];
__device__ float g_zn1[N_ROWS];
__device__ float g_enorm[K_CODES];
__device__ float g_tmin[N_ROWS * NT];
__device__ __align__(16) uint32_t g_mask[N_ROWS * NT * 4];
__device__ int   g_idx[N_ROWS];
__device__ float g_partial[4096];

__device__ __forceinline__ uint32_t smem_u32(const void* p) {
    uint32_t a;
    asm("{ .reg .u64 t; cvta.to.shared.u64 t, %1; cvt.u32.u64 %0, t; }" : "=r"(a) : "l"(p));
    return a;
}
#define LDM4(r, a) \
    asm volatile("ldmatrix.sync.aligned.m8n8.x4.shared.b16 {%0,%1,%2,%3}, [%4];" \
        : "=r"((r)[0]), "=r"((r)[1]), "=r"((r)[2]), "=r"((r)[3]) : "r"(a))
#define MMA16816(d, a, b0, b1) \
    asm volatile("mma.sync.aligned.m16n8k16.row.col.f32.bf16.bf16.f32 " \
        "{%0,%1,%2,%3}, {%4,%5,%6,%7}, {%8,%9}, {%0,%1,%2,%3};" \
        : "+f"((d)[0]), "+f"((d)[1]), "+f"((d)[2]), "+f"((d)[3]) \
        : "r"((a)[0]), "r"((a)[1]), "r"((a)[2]), "r"((a)[3]), "r"(b0), "r"(b1))

// ---------------- kernel 1: transpose + bf16 copy ---------------------------
__global__ void k_transpose(const float* __restrict__ z) {
    __shared__ float t[32][33];
    const int b = blockIdx.z, c0 = blockIdx.x * 32, hw0 = blockIdx.y * 32;
    const int tx = threadIdx.x & 31, ty = threadIdx.x >> 5;
    const float* zp = z + ((size_t)b * 256 + c0) * HW + hw0;
#pragma unroll
    for (int i = 0; i < 4; i++)
        t[ty + i * 8][tx] = zp[(size_t)(ty + i * 8) * HW + tx];
    __syncthreads();
    const size_t base = ((size_t)(b * HW + hw0)) * D_DIM + c0;
#pragma unroll
    for (int i = 0; i < 4; i++) {
        float v = t[tx][ty + i * 8];
        g_zt[base + (size_t)(ty + i * 8) * D_DIM + tx]  = v;
        g_zbf[base + (size_t)(ty + i * 8) * D_DIM + tx] = __float2bfloat16_rn(v);
    }
}

// ---------------- kernel 2: codebook -> bf16 ---------------------------------
__global__ void k_cbconv(const float* __restrict__ cb) {
    const int i = blockIdx.x * 256 + threadIdx.x;
    float4 v = ((const float4*)cb)[i];
    __nv_bfloat162 lo = {__float2bfloat16_rn(v.x), __float2bfloat16_rn(v.y)};
    __nv_bfloat162 hi = {__float2bfloat16_rn(v.z), __float2bfloat16_rn(v.w)};
    ((__nv_bfloat162*)g_cbbf)[i * 2]     = lo;
    ((__nv_bfloat162*)g_cbbf)[i * 2 + 1] = hi;
}

// ---------------- kernel 3: norms --------------------------------------------
__global__ void k_norms(const float* __restrict__ cb) {
    const int warp = (blockIdx.x * 256 + threadIdx.x) >> 5;
    const int lane = threadIdx.x & 31;
    const bool isz = warp < N_ROWS;
    const float* src = isz ? (g_zt + (size_t)warp * D_DIM)
                           : (cb + (size_t)(warp - N_ROWS) * D_DIM);
    float s = 0.f, s1 = 0.f;
#pragma unroll
    for (int i = 0; i < 8; i++) {
        float v = src[lane + i * 32];
        s  = fmaf(v, v, s);
        s1 += fabsf(v);
    }
#pragma unroll
    for (int o = 16; o; o >>= 1) {
        s  += __shfl_xor_sync(0xffffffffu, s, o);
        s1 += __shfl_xor_sync(0xffffffffu, s1, o);
    }
    if (lane == 0) {
        if (isz) { g_znorm[warp] = s; g_zn1[warp] = s1; }
        else       g_enorm[warp - N_ROWS] = s;
    }
}

// ---------------- kernel 4: HMMA bf16 screen GEMM + min/mask -----------------
#define SM_A    0
#define SM_B0   65536
#define SM_B1   131072
#define SM_SMIN 196608
#define SMEM_TOTAL 198656

// stage a 128x256 bf16 K-major tile into smem: 512B rows, 16B chunks XOR-swizzled
__device__ __forceinline__ void stage128(const __nv_bfloat16* __restrict__ g,
                                         char* s, int tid) {
#pragma unroll
    for (int it = 0; it < 16; it++) {
        const int idx = it * 256 + tid;
        const int row = idx >> 5, ch = idx & 31;
        const uint4 v = *(const uint4*)(g + (size_t)row * 256 + ch * 8);
        *(uint4*)(s + row * 512 + ((ch ^ (row & 7)) << 4)) = v;
    }
}

__global__ __launch_bounds__(256, 1) void k_screen() {
    extern __shared__ char smem[];
    const int tid = threadIdx.x, w = tid >> 5, lane = tid & 31;
    const int wm = (w >> 2) * 64, wn = (w & 3) * 32;
    const int gid = lane >> 2, tg = lane & 3;
    const int ls = lane & 7;
    const int row0 = blockIdx.x * 128;
    const uint32_t sb = smem_u32(smem);
    float* smin = (float*)(smem + SM_SMIN);

    stage128(g_zbf + (size_t)row0 * D_DIM, smem + SM_A, tid);
    stage128(g_cbbf, smem + SM_B0, tid);

    // per-thread row constants (fixed across tiles): k = i*2+h -> row
    int rows[8]; float znr[8], Trw[8];
#pragma unroll
    for (int k = 0; k < 8; k++) {
        const int r = wm + (k >> 1) * 16 + (k & 1) * 8 + gid;
        rows[k] = r;
        znr[k]  = g_znorm[row0 + r];
        Trw[k]  = g_zn1[row0 + r] * C1_T + C0_T;
    }

    // ldmatrix lane bases
    const int kmA = lane >> 4;          // A: k-half select (md>>1)
    const int kmB = (lane >> 3) & 1;    // B: k-half select (md&1)
    uint32_t baA[4];
#pragma unroll
    for (int i = 0; i < 4; i++) {
        const int r = wm + i * 16 + ((lane >> 3) & 1) * 8 + ls;
        baA[i] = sb + SM_A + r * 512;
    }
    uint32_t boff[2];
#pragma unroll
    for (int p = 0; p < 2; p++) {
        const int r = wn + (p * 2 + (lane >> 4)) * 8 + ls;
        boff[p] = r * 512;
    }

    float acc[4][4][4];
#pragma unroll
    for (int i = 0; i < 4; i++)
#pragma unroll
        for (int j = 0; j < 4; j++)
#pragma unroll
            for (int c = 0; c < 4; c++) acc[i][j][c] = 0.f;

    __syncthreads();

    for (int t = 0; t < NT; t++) {
        const uint32_t bbase = sb + ((t & 1) ? SM_B1 : SM_B0);
#pragma unroll 4
        for (int kc = 0; kc < 16; kc++) {
            uint32_t a[4][4], bq[2][4];
            const uint32_t offA = (uint32_t)(((2 * kc + kmA) ^ ls) << 4);
            const uint32_t offB = (uint32_t)(((2 * kc + kmB) ^ ls) << 4);
#pragma unroll
            for (int i = 0; i < 4; i++) LDM4(a[i], baA[i] + offA);
#pragma unroll
            for (int p = 0; p < 2; p++) LDM4(bq[p], bbase + boff[p] + offB);
#pragma unroll
            for (int i = 0; i < 4; i++) {
#pragma unroll
                for (int j = 0; j < 4; j++)
                    MMA16816(acc[i][j], a[i], bq[j >> 1][(j & 1) * 2],
                             bq[j >> 1][(j & 1) * 2 + 1]);
            }
        }
        if (t + 1 < NT)
            stage128(g_cbbf + (size_t)(t + 1) * 128 * D_DIM,
                     smem + (((t + 1) & 1) ? SM_B1 : SM_B0), tid);

        // ---- epilogue (register-resident) ----
        float2 en[4];
        const float2* ep = (const float2*)(g_enorm + t * 128 + wn);
#pragma unroll
        for (int j = 0; j < 4; j++) en[j] = __ldg(ep + j * 4 + tg);

        float rmin[8];
#pragma unroll
        for (int k = 0; k < 8; k++) rmin[k] = CUDART_INF_F;
#pragma unroll
        for (int i = 0; i < 4; i++)
#pragma unroll
            for (int j = 0; j < 4; j++)
#pragma unroll
                for (int c = 0; c < 4; c++) {
                    const int k = i * 2 + (c >> 1);
                    const float zne = znr[k] + ((c & 1) ? en[j].y : en[j].x);
                    const float s = fmaf(-2.f, acc[i][j][c], zne);
                    rmin[k] = fminf(rmin[k], s);
                }
#pragma unroll
        for (int k = 0; k < 8; k++) {
            rmin[k] = fminf(rmin[k], __shfl_xor_sync(0xffffffffu, rmin[k], 1));
            rmin[k] = fminf(rmin[k], __shfl_xor_sync(0xffffffffu, rmin[k], 2));
        }
        if (tg == 0) {
#pragma unroll
            for (int k = 0; k < 8; k++) smin[rows[k] * 4 + (w & 3)] = rmin[k];
        }
        __syncthreads();
#pragma unroll
        for (int k = 0; k < 8; k++) {
            const float* sp = &smin[rows[k] * 4];
            const float gm = fminf(fminf(sp[0], sp[1]), fminf(sp[2], sp[3]));
            const float th = gm + Trw[k];
            const int i = k >> 1, h = k & 1;
            uint32_t m = 0;
#pragma unroll
            for (int j = 0; j < 4; j++) {
                const float s0 = fmaf(-2.f, acc[i][j][h * 2],     znr[k] + en[j].x);
                const float s1 = fmaf(-2.f, acc[i][j][h * 2 + 1], znr[k] + en[j].y);
                if (s0 < th) m |= 1u << (j * 8 + tg * 2);
                if (s1 < th) m |= 1u << (j * 8 + tg * 2 + 1);
            }
            m |= __shfl_xor_sync(0xffffffffu, m, 1);
            m |= __shfl_xor_sync(0xffffffffu, m, 2);
            if (tg == 0) {
                g_mask[((size_t)(row0 + rows[k]) * NT + t) * 4 + (w & 3)] = m;
                if ((w & 3) == 0) g_tmin[(size_t)(row0 + rows[k]) * NT + t] = gm;
            }
        }
#pragma unroll
        for (int i = 0; i < 4; i++)
#pragma unroll
            for (int j = 0; j < 4; j++)
#pragma unroll
                for (int c = 0; c < 4; c++) acc[i][j][c] = 0.f;
        __syncthreads();
    }
}

// ---------------- kernel 5: exact rescore of flagged candidates --------------
__global__ void k_rescore(const float* __restrict__ cb, float* __restrict__ oidx) {
    __shared__ float zrow[256];
    __shared__ float smin2[64];
    __shared__ float sd[64];
    __shared__ int   si[64];
    const int row = blockIdx.x, tid = threadIdx.x;
    const float tm = g_tmin[(size_t)row * NT + tid];
    smin2[tid] = tm;
#pragma unroll
    for (int i = tid; i < 256; i += 64) zrow[i] = g_zt[(size_t)row * D_DIM + i];
    __syncthreads();
    for (int o = 32; o; o >>= 1) {
        if (tid < o) smin2[tid] = fminf(smin2[tid], smin2[tid + o]);
        __syncthreads();
    }
    const float m    = smin2[0];
    const float Trow = g_zn1[row] * C1_T + C0_T;
    const float zn   = g_znorm[row];

    float bd = CUDART_INF_F; int bi = 0x7fffffff;
    if (tm < m + Trow) {
        const uint32_t* M = &g_mask[((size_t)row * NT + tid) * 4];
        for (int q = 0; q < 4; q++) {
            uint32_t bits = M[q];
            while (bits) {
                const int j = __ffs(bits) - 1; bits &= bits - 1;
                const int k = tid * 128 + q * 32 + j;
                const float* e = cb + (size_t)k * D_DIM;
                float acc = 0.f;
#pragma unroll 8
                for (int d0 = 0; d0 < 256; d0++)
                    acc = fmaf(zrow[d0], __ldg(e + d0), acc);   // EXACT serial order
                const float s   = zn + __ldg(&g_enorm[k]);
                const float dsc = s - 2.0f * acc;
                if (dsc < bd || (dsc == bd && k < bi)) { bd = dsc; bi = k; }
            }
        }
    }
    sd[tid] = bd; si[tid] = bi;
    __syncthreads();
    for (int o = 32; o; o >>= 1) {
        if (tid < o) {
            const float d2 = sd[tid + o]; const int i2 = si[tid + o];
            if (d2 < sd[tid] || (d2 == sd[tid] && i2 < si[tid])) { sd[tid] = d2; si[tid] = i2; }
        }
        __syncthreads();
    }
    if (tid == 0) { g_idx[row] = si[0]; oidx[row] = (float)si[0]; }
}

// ---------------- kernel 6: gather + straight-through + loss partials --------
__global__ void k_gather(const float* __restrict__ z, const float* __restrict__ cb,
                         float* __restrict__ out) {
    const int c = blockIdx.x, b = blockIdx.y;
    const float* zp = z   + ((size_t)b * D_DIM + c) * HW;
    float*       op = out + ((size_t)b * D_DIM + c) * HW;
    float part = 0.f;
#pragma unroll
    for (int it = 0; it < 4; it++) {
        const int hw  = it * 256 + threadIdx.x;
        const int idx = g_idx[b * HW + hw];
        float q  = __ldg(cb + (size_t)idx * D_DIM + c);
        float zv = zp[hw];
        float t  = q - zv;
        op[hw]   = zv + t;
        part     = fmaf(t, t, part);
    }
    __shared__ float sm[8];
    const int lane = threadIdx.x & 31, ww = threadIdx.x >> 5;
#pragma unroll
    for (int o = 16; o; o >>= 1) part += __shfl_xor_sync(0xffffffffu, part, o);
    if (lane == 0) sm[ww] = part;
    __syncthreads();
    if (threadIdx.x == 0) {
        float s = 0.f;
        for (int i = 0; i < 8; i++) s += sm[i];
        g_partial[b * 256 + c] = s;
    }
}

// ---------------- kernel 7: loss finalize ------------------------------------
__global__ void k_loss(float* __restrict__ out) {
    __shared__ float sm[256];
    const int tid = threadIdx.x;
    float s = 0.f;
#pragma unroll
    for (int i = 0; i < 16; i++) s += g_partial[tid * 16 + i];
    sm[tid] = s;
    __syncthreads();
    for (int o = 128; o; o >>= 1) {
        if (tid < o) sm[tid] += sm[tid + o];
        __syncthreads();
    }
    if (tid == 0) {
        float m = sm[0] / (float)ZQ_ELEMS;
        out[ZQ_ELEMS] = m + 0.25f * m;
    }
}

// ---------------- launcher ---------------------------------------------------
extern "C" void kernel_launch(void* const* d_in, const int* in_sizes, int n_in,
                              void* d_out, int out_size) {
    const float* z  = (const float*)d_in[0];
    const float* cb = (const float*)d_in[1];
    float* out = (float*)d_out;

    static int attr_set = 0;
    if (!attr_set) {
        cudaFuncSetAttribute(k_screen, cudaFuncAttributeMaxDynamicSharedMemorySize,
                             SMEM_TOTAL);
        attr_set = 1;
    }

    dim3 gT(8, 32, 16);
    k_transpose<<<gT, 256>>>(z);
    k_cbconv<<<2048, 256>>>(cb);
    k_norms<<<(N_ROWS + K_CODES) / 8, 256>>>(cb);
    k_screen<<<128, 256, SMEM_TOTAL>>>();
    k_rescore<<<N_ROWS, 64>>>(cb, out + ZQ_ELEMS + 1);
    dim3 gG(256, 16);
    k_gather<<<gG, 256>>>(z, cb, out);
    k_loss<<<1, 256>>>(out);
}

// round 4
// speedup vs baseline: 5.7659x; 1.0888x over previous
#include <cuda_runtime.h>
#include <cuda_bf16.h>
#include <math_constants.h>
#include <cstdint>

#define N_ROWS  16384       // b*h*w
#define D_DIM   256
#define K_CODES 8192
#define HW      1024
#define ZQ_ELEMS (16 * 256 * 1024)
#define NT      64          // code tiles of 128
#define C1_T    1.25e-6f    // per-row error slope (covers bf16 rounding of z,e)
#define C0_T    1.6e-4f     // fixed slack: fp32 reorder + expr rounding + grid ulps

// ---------------- scratch ----------------------------------------------------
__device__ __align__(16) float          g_zt[N_ROWS * D_DIM];
__device__ __align__(16) __nv_bfloat16  g_zbf[N_ROWS * D_DIM];
__device__ __align__(16) __nv_bfloat16  g_cbbf[K_CODES * D_DIM];
__device__ float g_znorm[N_ROWS];
__device__ float g_zn1[N_ROWS];
__device__ float g_enorm[K_CODES];
__device__ float g_tmin[N_ROWS * NT];
__device__ __align__(16) uint32_t g_mask[N_ROWS * NT * 4];
__device__ int   g_idx[N_ROWS];
__device__ float g_partial[4096];

__device__ __forceinline__ uint32_t smem_u32(const void* p) {
    uint32_t a;
    asm("{ .reg .u64 t; cvta.to.shared.u64 t, %1; cvt.u32.u64 %0, t; }" : "=r"(a) : "l"(p));
    return a;
}
#define LDM4(r, a) \
    asm volatile("ldmatrix.sync.aligned.m8n8.x4.shared.b16 {%0,%1,%2,%3}, [%4];" \
        : "=r"((r)[0]), "=r"((r)[1]), "=r"((r)[2]), "=r"((r)[3]) : "r"(a))
#define MMA16816(d, a, b0, b1) \
    asm volatile("mma.sync.aligned.m16n8k16.row.col.f32.bf16.bf16.f32 " \
        "{%0,%1,%2,%3}, {%4,%5,%6,%7}, {%8,%9}, {%0,%1,%2,%3};" \
        : "+f"((d)[0]), "+f"((d)[1]), "+f"((d)[2]), "+f"((d)[3]) \
        : "r"((a)[0]), "r"((a)[1]), "r"((a)[2]), "r"((a)[3]), "r"(b0), "r"(b1))
#define CP_ASYNC16(s, g) \
    asm volatile("cp.async.cg.shared.global [%0], [%1], 16;" :: "r"(s), "l"(g) : "memory")
#define CP_COMMIT()  asm volatile("cp.async.commit_group;" ::: "memory")
#define CP_WAIT0()   asm volatile("cp.async.wait_group 0;" ::: "memory")

// ---------------- kernel 1: transpose + bf16 copy ---------------------------
__global__ void k_transpose(const float* __restrict__ z) {
    __shared__ float t[32][33];
    const int b = blockIdx.z, c0 = blockIdx.x * 32, hw0 = blockIdx.y * 32;
    const int tx = threadIdx.x & 31, ty = threadIdx.x >> 5;
    const float* zp = z + ((size_t)b * 256 + c0) * HW + hw0;
#pragma unroll
    for (int i = 0; i < 4; i++)
        t[ty + i * 8][tx] = zp[(size_t)(ty + i * 8) * HW + tx];
    __syncthreads();
    const size_t base = ((size_t)(b * HW + hw0)) * D_DIM + c0;
#pragma unroll
    for (int i = 0; i < 4; i++) {
        float v = t[tx][ty + i * 8];
        g_zt[base + (size_t)(ty + i * 8) * D_DIM + tx]  = v;
        g_zbf[base + (size_t)(ty + i * 8) * D_DIM + tx] = __float2bfloat16_rn(v);
    }
}

// ---------------- kernel 2: codebook -> bf16 + enorm (fused) -----------------
__global__ void k_cbprep(const float* __restrict__ cb) {
    const int warp = (blockIdx.x * 256 + threadIdx.x) >> 5;   // 0..8191
    const int lane = threadIdx.x & 31;
    const float* src = cb + (size_t)warp * D_DIM;
    float s = 0.f;
#pragma unroll
    for (int i = 0; i < 8; i++) {
        float v = src[lane + i * 32];
        s = fmaf(v, v, s);
    }
#pragma unroll
    for (int o = 16; o; o >>= 1) s += __shfl_xor_sync(0xffffffffu, s, o);
    if (lane == 0) g_enorm[warp] = s;

    float4 v0 = *(const float4*)(src + lane * 8);
    float4 v1 = *(const float4*)(src + lane * 8 + 4);
    __nv_bfloat162 p0{__float2bfloat16_rn(v0.x), __float2bfloat16_rn(v0.y)};
    __nv_bfloat162 p1{__float2bfloat16_rn(v0.z), __float2bfloat16_rn(v0.w)};
    __nv_bfloat162 p2{__float2bfloat16_rn(v1.x), __float2bfloat16_rn(v1.y)};
    __nv_bfloat162 p3{__float2bfloat16_rn(v1.z), __float2bfloat16_rn(v1.w)};
    uint4 o;
    o.x = *(uint32_t*)&p0; o.y = *(uint32_t*)&p1;
    o.z = *(uint32_t*)&p2; o.w = *(uint32_t*)&p3;
    *(uint4*)(g_cbbf + (size_t)warp * D_DIM + lane * 8) = o;
}

// ---------------- kernel 3: z norms (unchanged arithmetic) -------------------
__global__ void k_norms(const float* __restrict__ unused) {
    const int warp = (blockIdx.x * 256 + threadIdx.x) >> 5;   // 0..16383
    const int lane = threadIdx.x & 31;
    const float* src = g_zt + (size_t)warp * D_DIM;
    float s = 0.f, s1 = 0.f;
#pragma unroll
    for (int i = 0; i < 8; i++) {
        float v = src[lane + i * 32];
        s  = fmaf(v, v, s);
        s1 += fabsf(v);
    }
#pragma unroll
    for (int o = 16; o; o >>= 1) {
        s  += __shfl_xor_sync(0xffffffffu, s, o);
        s1 += __shfl_xor_sync(0xffffffffu, s1, o);
    }
    if (lane == 0) { g_znorm[warp] = s; g_zn1[warp] = s1; }
}

// ---------------- kernel 4: HMMA bf16 screen GEMM + min/mask -----------------
#define SM_A    0
#define SM_B0   65536
#define SM_B1   131072
#define SM_SMIN 196608
#define SMEM_TOTAL 198656

// async-stage a 128x256 bf16 K-major tile: 512B rows, 16B chunks XOR-swizzled
__device__ __forceinline__ void stage_async(const __nv_bfloat16* __restrict__ g,
                                            uint32_t sdst, int tid) {
#pragma unroll
    for (int it = 0; it < 8; it++) {
        const int idx = it * 512 + tid;
        const int row = idx >> 5, ch = idx & 31;
        CP_ASYNC16(sdst + row * 512 + ((ch ^ (row & 7)) << 4),
                   g + (size_t)row * 256 + ch * 8);
    }
}

__global__ __launch_bounds__(512, 1) void k_screen() {
    extern __shared__ char smem[];
    const int tid = threadIdx.x, w = tid >> 5, lane = tid & 31;
    const int wm = (w >> 2) * 32, wc = w & 3, wn = wc * 32;
    const int gid = lane >> 2, tg = lane & 3, ls = lane & 7;
    const int row0 = blockIdx.x * 128;
    const uint32_t sb = smem_u32(smem);
    float* smin = (float*)(smem + SM_SMIN);

    stage_async(g_zbf + (size_t)row0 * D_DIM, sb + SM_A, tid);
    stage_async(g_cbbf, sb + SM_B0, tid);
    CP_COMMIT();

    int rows[4]; float znr[4], Trw[4];
#pragma unroll
    for (int k = 0; k < 4; k++) {
        const int r = wm + (k >> 1) * 16 + (k & 1) * 8 + gid;
        rows[k] = r;
        znr[k]  = g_znorm[row0 + r];
        Trw[k]  = g_zn1[row0 + r] * C1_T + C0_T;
    }

    const int kmA = lane >> 4;
    const int kmB = (lane >> 3) & 1;
    uint32_t baA[2];
#pragma unroll
    for (int i = 0; i < 2; i++) {
        const int r = wm + i * 16 + ((lane >> 3) & 1) * 8 + ls;
        baA[i] = sb + SM_A + r * 512;
    }
    uint32_t boff[2];
#pragma unroll
    for (int p = 0; p < 2; p++) {
        const int r = wn + (p * 2 + (lane >> 4)) * 8 + ls;
        boff[p] = r * 512;
    }

    float acc[2][4][4];
#pragma unroll
    for (int i = 0; i < 2; i++)
#pragma unroll
        for (int j = 0; j < 4; j++)
#pragma unroll
            for (int c = 0; c < 4; c++) acc[i][j][c] = 0.f;

    CP_WAIT0();
    __syncthreads();

    for (int t = 0; t < NT; t++) {
        const uint32_t bbase = sb + ((t & 1) ? SM_B1 : SM_B0);
        if (t + 1 < NT) {
            stage_async(g_cbbf + (size_t)(t + 1) * 128 * D_DIM,
                        sb + (((t + 1) & 1) ? SM_B1 : SM_B0), tid);
            CP_COMMIT();
        }
#pragma unroll 4
        for (int kc = 0; kc < 16; kc++) {
            uint32_t a[2][4], bq[2][4];
            const uint32_t offA = (uint32_t)(((2 * kc + kmA) ^ ls) << 4);
            const uint32_t offB = (uint32_t)(((2 * kc + kmB) ^ ls) << 4);
            LDM4(a[0], baA[0] + offA);
            LDM4(a[1], baA[1] + offA);
            LDM4(bq[0], bbase + boff[0] + offB);
            LDM4(bq[1], bbase + boff[1] + offB);
#pragma unroll
            for (int i = 0; i < 2; i++)
#pragma unroll
                for (int j = 0; j < 4; j++)
                    MMA16816(acc[i][j], a[i], bq[j >> 1][(j & 1) * 2],
                             bq[j >> 1][(j & 1) * 2 + 1]);
        }

        // ---- epilogue ----
        float2 en[4];
        const float2* ep = (const float2*)(g_enorm + t * 128 + wn);
#pragma unroll
        for (int j = 0; j < 4; j++) en[j] = __ldg(ep + j * 4 + tg);

        float rmin[4];
#pragma unroll
        for (int k = 0; k < 4; k++) rmin[k] = CUDART_INF_F;
#pragma unroll
        for (int i = 0; i < 2; i++)
#pragma unroll
            for (int j = 0; j < 4; j++)
#pragma unroll
                for (int c = 0; c < 4; c++) {
                    const int k = i * 2 + (c >> 1);
                    const float zne = znr[k] + ((c & 1) ? en[j].y : en[j].x);
                    const float s = fmaf(-2.f, acc[i][j][c], zne);
                    rmin[k] = fminf(rmin[k], s);
                }
#pragma unroll
        for (int k = 0; k < 4; k++) {
            rmin[k] = fminf(rmin[k], __shfl_xor_sync(0xffffffffu, rmin[k], 1));
            rmin[k] = fminf(rmin[k], __shfl_xor_sync(0xffffffffu, rmin[k], 2));
        }
        if (tg == 0) {
#pragma unroll
            for (int k = 0; k < 4; k++) smin[rows[k] * 4 + wc] = rmin[k];
        }
        __syncthreads();
#pragma unroll
        for (int k = 0; k < 4; k++) {
            const float* sp = &smin[rows[k] * 4];
            const float gm = fminf(fminf(sp[0], sp[1]), fminf(sp[2], sp[3]));
            const float th = gm + Trw[k];
            const int i = k >> 1, h = k & 1;
            uint32_t m = 0;
#pragma unroll
            for (int j = 0; j < 4; j++) {
                const float s0 = fmaf(-2.f, acc[i][j][h * 2],     znr[k] + en[j].x);
                const float s1 = fmaf(-2.f, acc[i][j][h * 2 + 1], znr[k] + en[j].y);
                if (s0 < th) m |= 1u << (j * 8 + tg * 2);
                if (s1 < th) m |= 1u << (j * 8 + tg * 2 + 1);
            }
            m |= __shfl_xor_sync(0xffffffffu, m, 1);
            m |= __shfl_xor_sync(0xffffffffu, m, 2);
            if (tg == 0) {
                g_mask[((size_t)(row0 + rows[k]) * NT + t) * 4 + wc] = m;
                if (wc == 0) g_tmin[(size_t)(row0 + rows[k]) * NT + t] = gm;
            }
        }
#pragma unroll
        for (int i = 0; i < 2; i++)
#pragma unroll
            for (int j = 0; j < 4; j++)
#pragma unroll
                for (int c = 0; c < 4; c++) acc[i][j][c] = 0.f;
        CP_WAIT0();
        __syncthreads();
    }
}

// ---------------- kernel 5: exact rescore of flagged candidates --------------
__global__ void k_rescore(const float* __restrict__ cb, float* __restrict__ oidx) {
    __shared__ float zrow[256];
    __shared__ float smin2[64];
    __shared__ float sd[64];
    __shared__ int   si[64];
    const int row = blockIdx.x, tid = threadIdx.x;
    const float tm = g_tmin[(size_t)row * NT + tid];
    smin2[tid] = tm;
#pragma unroll
    for (int i = tid; i < 256; i += 64) zrow[i] = g_zt[(size_t)row * D_DIM + i];
    __syncthreads();
    for (int o = 32; o; o >>= 1) {
        if (tid < o) smin2[tid] = fminf(smin2[tid], smin2[tid + o]);
        __syncthreads();
    }
    const float m    = smin2[0];
    const float Trow = g_zn1[row] * C1_T + C0_T;
    const float zn   = g_znorm[row];

    float bd = CUDART_INF_F; int bi = 0x7fffffff;
    if (tm < m + Trow) {
        const uint32_t* M = &g_mask[((size_t)row * NT + tid) * 4];
        for (int q = 0; q < 4; q++) {
            uint32_t bits = M[q];
            while (bits) {
                const int j = __ffs(bits) - 1; bits &= bits - 1;
                const int k = tid * 128 + q * 32 + j;
                const float* e = cb + (size_t)k * D_DIM;
                float acc = 0.f;
#pragma unroll 8
                for (int d0 = 0; d0 < 256; d0++)
                    acc = fmaf(zrow[d0], __ldg(e + d0), acc);   // EXACT serial order
                const float s   = zn + __ldg(&g_enorm[k]);
                const float dsc = s - 2.0f * acc;
                if (dsc < bd || (dsc == bd && k < bi)) { bd = dsc; bi = k; }
            }
        }
    }
    sd[tid] = bd; si[tid] = bi;
    __syncthreads();
    for (int o = 32; o; o >>= 1) {
        if (tid < o) {
            const float d2 = sd[tid + o]; const int i2 = si[tid + o];
            if (d2 < sd[tid] || (d2 == sd[tid] && i2 < si[tid])) { sd[tid] = d2; si[tid] = i2; }
        }
        __syncthreads();
    }
    if (tid == 0) { g_idx[row] = si[0]; oidx[row] = (float)si[0]; }
}

// ---------------- kernel 6: gather + straight-through + loss partials --------
__global__ void k_gather(const float* __restrict__ z, const float* __restrict__ cb,
                         float* __restrict__ out) {
    const int c = blockIdx.x, b = blockIdx.y;
    const float* zp = z   + ((size_t)b * D_DIM + c) * HW;
    float*       op = out + ((size_t)b * D_DIM + c) * HW;
    float part = 0.f;
#pragma unroll
    for (int it = 0; it < 4; it++) {
        const int hw  = it * 256 + threadIdx.x;
        const int idx = g_idx[b * HW + hw];
        float q  = __ldg(cb + (size_t)idx * D_DIM + c);
        float zv = zp[hw];
        float t  = q - zv;
        op[hw]   = zv + t;
        part     = fmaf(t, t, part);
    }
    __shared__ float sm[8];
    const int lane = threadIdx.x & 31, ww = threadIdx.x >> 5;
#pragma unroll
    for (int o = 16; o; o >>= 1) part += __shfl_xor_sync(0xffffffffu, part, o);
    if (lane == 0) sm[ww] = part;
    __syncthreads();
    if (threadIdx.x == 0) {
        float s = 0.f;
        for (int i = 0; i < 8; i++) s += sm[i];
        g_partial[b * 256 + c] = s;
    }
}

// ---------------- kernel 7: loss finalize ------------------------------------
__global__ void k_loss(float* __restrict__ out) {
    __shared__ float sm[256];
    const int tid = threadIdx.x;
    float s = 0.f;
#pragma unroll
    for (int i = 0; i < 16; i++) s += g_partial[tid * 16 + i];
    sm[tid] = s;
    __syncthreads();
    for (int o = 128; o; o >>= 1) {
        if (tid < o) sm[tid] += sm[tid + o];
        __syncthreads();
    }
    if (tid == 0) {
        float m = sm[0] / (float)ZQ_ELEMS;
        out[ZQ_ELEMS] = m + 0.25f * m;
    }
}

// ---------------- launcher ---------------------------------------------------
extern "C" void kernel_launch(void* const* d_in, const int* in_sizes, int n_in,
                              void* d_out, int out_size) {
    const float* z  = (const float*)d_in[0];
    const float* cb = (const float*)d_in[1];
    float* out = (float*)d_out;

    static int attr_set = 0;
    if (!attr_set) {
        cudaFuncSetAttribute(k_screen, cudaFuncAttributeMaxDynamicSharedMemorySize,
                             SMEM_TOTAL);
        attr_set = 1;
    }

    dim3 gT(8, 32, 16);
    k_transpose<<<gT, 256>>>(z);
    k_cbprep<<<1024, 256>>>(cb);
    k_norms<<<2048, 256>>>(nullptr);
    k_screen<<<128, 512, SMEM_TOTAL>>>();
    k_rescore<<<N_ROWS, 64>>>(cb, out + ZQ_ELEMS + 1);
    dim3 gG(256, 16);
    k_gather<<<gG, 256>>>(z, cb, out);
    k_loss<<<1, 256>>>(out);
}